// round 16
// baseline (speedup 1.0000x reference)
#include <cuda_runtime.h>
#include <cuda_bf16.h>
#include <math.h>
#include <stdint.h>

// Problem constants (fixed by the dataset)
#define NDRUGS 8192
#define KDIM   256
#define LOG2F_ 0.69314718055994531f

// ============================ device scratch ================================
__device__ __align__(1024) __nv_bfloat16 g_genc_bf[NDRUGS * KDIM];
__device__ __align__(1024) __nv_bfloat16 g_lenc_bf[NDRUGS * KDIM];
__device__ __align__(1024) __nv_bfloat16 g_wT[8 * KDIM * KDIM];   // bf16 W^T
__device__ __align__(1024) char  g_genc_i8[NDRUGS * KDIM];        // int8 enc
__device__ __align__(1024) char  g_lenc_i8[NDRUGS * KDIM];
__device__ float g_sB[NDRUGS];   // per-row scale of g_enc (j / columns)
__device__ float g_sA[NDRUGS];   // per-row scale of l_enc (i / rows)

#define BT   128
#define NBLK ((NDRUGS / BT) * (NDRUGS / BT))   // 64*64 = 4096
__device__ float g_partials[2 * NBLK];
__device__ unsigned int g_done;                // zero-init; self-resetting

// =========================== small PTX helpers ==============================
__device__ __forceinline__ uint32_t smem_u32(const void* p) {
    uint32_t a;
    asm("{ .reg .u64 t; cvta.to.shared.u64 t, %1; cvt.u32.u64 %0, t; }"
        : "=r"(a) : "l"(p));
    return a;
}
__device__ __forceinline__ void cp_async16(uint32_t dst, const void* src) {
    asm volatile("cp.async.cg.shared.global [%0], [%1], 16;"
                 :: "r"(dst), "l"(src) : "memory");
}
__device__ __forceinline__ void cp_async_commit() {
    asm volatile("cp.async.commit_group;" ::: "memory");
}
template <int N>
__device__ __forceinline__ void cp_async_wait() {
    asm volatile("cp.async.wait_group %0;" :: "n"(N) : "memory");
}
__device__ __forceinline__ void prefetch_l2(const void* p) {
    asm volatile("prefetch.global.L2 [%0];" :: "l"(p));
}
__device__ __forceinline__ void ldmatrix_x4(uint32_t& r0, uint32_t& r1,
                                            uint32_t& r2, uint32_t& r3,
                                            uint32_t addr) {
    asm volatile("ldmatrix.sync.aligned.m8n8.x4.shared.b16 {%0,%1,%2,%3}, [%4];"
                 : "=r"(r0), "=r"(r1), "=r"(r2), "=r"(r3) : "r"(addr));
}
__device__ __forceinline__ void mma_bf16(float& d0, float& d1, float& d2, float& d3,
                                         uint32_t a0, uint32_t a1, uint32_t a2,
                                         uint32_t a3, uint32_t b0, uint32_t b1) {
    asm volatile(
        "mma.sync.aligned.m16n8k16.row.col.f32.bf16.bf16.f32 "
        "{%0,%1,%2,%3}, {%4,%5,%6,%7}, {%8,%9}, {%0,%1,%2,%3};"
        : "+f"(d0), "+f"(d1), "+f"(d2), "+f"(d3)
        : "r"(a0), "r"(a1), "r"(a2), "r"(a3), "r"(b0), "r"(b1));
}
__device__ __forceinline__ void mma_s8(int& d0, int& d1, int& d2, int& d3,
                                       uint32_t a0, uint32_t a1, uint32_t a2,
                                       uint32_t a3, uint32_t b0, uint32_t b1) {
    asm volatile(
        "mma.sync.aligned.m16n8k32.row.col.s32.s8.s8.s32 "
        "{%0,%1,%2,%3}, {%4,%5,%6,%7}, {%8,%9}, {%0,%1,%2,%3};"
        : "+r"(d0), "+r"(d1), "+r"(d2), "+r"(d3)
        : "r"(a0), "r"(a1), "r"(a2), "r"(a3), "r"(b0), "r"(b1));
}
__device__ __forceinline__ uint32_t pack_bf2(float a, float b) {
    __nv_bfloat162 h = __floats2bfloat162_rn(a, b);
    return *(uint32_t*)&h;
}

// ============================================================================
// Weight transpose + bf16 convert (unchanged)
// ============================================================================
__global__ void __launch_bounds__(256)
wT_kernel(const float* __restrict__ m0, const float* __restrict__ m1,
          const float* __restrict__ m2, const float* __restrict__ m3,
          const float* __restrict__ m4, const float* __restrict__ m5,
          const float* __restrict__ m6, const float* __restrict__ m7)
{
    const float* srcs[8] = {m0, m1, m2, m3, m4, m5, m6, m7};
    const float* w = srcs[blockIdx.y];
    __nv_bfloat16* dst = g_wT + (size_t)blockIdx.y * KDIM * KDIM;

    __shared__ float t[32][33];
    const int tid = threadIdx.x;
    const int k0 = (blockIdx.x & 7) * 32;
    const int n0 = (blockIdx.x >> 3) * 32;

#pragma unroll
    for (int i = tid; i < 32 * 32; i += 256) {
        int r = i >> 5, c = i & 31;
        t[r][c] = w[(size_t)(k0 + r) * KDIM + n0 + c];
    }
    __syncthreads();
#pragma unroll
    for (int i = tid; i < 32 * 32; i += 256) {
        int r = i >> 5, c = i & 31;
        dst[(size_t)(n0 + r) * KDIM + k0 + c] = __float2bfloat16(t[c][r]);
    }
}

// ============================================================================
// Fused FF encoder via mma.sync (unchanged from R15)
// ============================================================================
#define FF_LDX  264
#define FF_LDW  72
#define FF_X    0
#define FF_TMP  33792
#define FF_W    67584
#define FF_SMEM 104448

__device__ __forceinline__ void ff_gemm(
    char* smem, uint32_t s_base, int mode,
    const __nv_bfloat16* __restrict__ wmat, const float* __restrict__ bias,
    __nv_bfloat16* __restrict__ gout, int row0,
    int tid, int mrow, int ncol, int gid, int tig,
    uint32_t aL, uint32_t bL)
{
    float acc[2][8][4];
#pragma unroll
    for (int mt = 0; mt < 2; mt++)
#pragma unroll
        for (int nt = 0; nt < 8; nt++)
#pragma unroll
            for (int q = 0; q < 4; q++) acc[mt][nt][q] = 0.f;

    const int wrow = tid >> 3;
    const int wkq  = (tid & 7) * 8;
    auto issueW = [&](int kc) {
        const uint32_t w_s = s_base + FF_W;
#pragma unroll
        for (int it = 0; it < 8; it++) {
            int row = wrow + it * 32;
            cp_async16(w_s + (uint32_t)(row * FF_LDW + wkq) * 2,
                       wmat + (size_t)row * KDIM + kc * 64 + wkq);
        }
        cp_async_commit();
    };

#pragma unroll 1
    for (int kc = 0; kc < 4; kc++) {
        issueW(kc);
        cp_async_wait<0>();
        __syncthreads();

        const uint32_t a_s = s_base + FF_X + aL;
        const uint32_t b_s = s_base + FF_W + bL;
#pragma unroll
        for (int ks = 0; ks < 4; ks++) {
            const uint32_t ak = (uint32_t)((kc * 64 + ks * 16) * 2);
            const uint32_t bk = (uint32_t)(ks * 16 * 2);
            uint32_t bfr[8][2];
#pragma unroll
            for (int ntp = 0; ntp < 4; ntp++) {
                uint32_t r0, r1, r2, r3;
                ldmatrix_x4(r0, r1, r2, r3,
                            b_s + (uint32_t)(ntp * 16 * FF_LDW) * 2 + bk);
                bfr[2 * ntp][0]     = r0; bfr[2 * ntp][1]     = r1;
                bfr[2 * ntp + 1][0] = r2; bfr[2 * ntp + 1][1] = r3;
            }
#pragma unroll
            for (int mt = 0; mt < 2; mt++) {
                uint32_t a0, a1, a2, a3;
                ldmatrix_x4(a0, a1, a2, a3,
                            a_s + (uint32_t)(mt * 16 * FF_LDX) * 2 + ak);
#pragma unroll
                for (int nt = 0; nt < 8; nt++)
                    mma_bf16(acc[mt][nt][0], acc[mt][nt][1],
                             acc[mt][nt][2], acc[mt][nt][3],
                             a0, a1, a2, a3, bfr[nt][0], bfr[nt][1]);
            }
        }
        __syncthreads();
    }

#pragma unroll
    for (int mt = 0; mt < 2; mt++) {
        const int r = mrow + mt * 16 + gid;
#pragma unroll
        for (int nt = 0; nt < 8; nt++) {
            const int c0 = ncol + nt * 8 + tig * 2;
            float bv0 = __ldg(bias + c0), bv1 = __ldg(bias + c0 + 1);
            float d0 = acc[mt][nt][0] + bv0, d1 = acc[mt][nt][1] + bv1;
            float d2 = acc[mt][nt][2] + bv0, d3 = acc[mt][nt][3] + bv1;
            const uint32_t off_lo = (uint32_t)(r * FF_LDX + c0) * 2;
            const uint32_t off_hi = (uint32_t)((r + 8) * FF_LDX + c0) * 2;
            if (mode == 0) {
                *(uint32_t*)(smem + FF_TMP + off_lo) = pack_bf2(d0, d1);
                *(uint32_t*)(smem + FF_TMP + off_hi) = pack_bf2(d2, d3);
            } else if (mode == 1) {
                *(uint32_t*)(smem + FF_X + off_lo) =
                    pack_bf2(fmaxf(d0, 0.f), fmaxf(d1, 0.f));
                *(uint32_t*)(smem + FF_X + off_hi) =
                    pack_bf2(fmaxf(d2, 0.f), fmaxf(d3, 0.f));
            } else {
                uint32_t ulo = *(const uint32_t*)(smem + FF_TMP + off_lo);
                uint32_t uhi = *(const uint32_t*)(smem + FF_TMP + off_hi);
                float2 t0 = __bfloat1622float2(*(__nv_bfloat162*)&ulo);
                float2 t1 = __bfloat1622float2(*(__nv_bfloat162*)&uhi);
                *(uint32_t*)(gout + (size_t)(row0 + r) * KDIM + c0) =
                    pack_bf2(fmaxf(d0, 0.f) + t0.x, fmaxf(d1, 0.f) + t0.y);
                *(uint32_t*)(gout + (size_t)(row0 + r + 8) * KDIM + c0) =
                    pack_bf2(fmaxf(d2, 0.f) + t1.x, fmaxf(d3, 0.f) + t1.y);
            }
        }
    }
    __syncthreads();
}

__global__ void __launch_bounds__(256, 2)
ff_mma_kernel(const float* __restrict__ xg, const float* __restrict__ xl,
              const float* __restrict__ gb1, const float* __restrict__ gb2,
              const float* __restrict__ gb3, const float* __restrict__ gbs,
              const float* __restrict__ lb1, const float* __restrict__ lb2,
              const float* __restrict__ lb3, const float* __restrict__ lbs)
{
    extern __shared__ char smem[];
    const uint32_t s_base = smem_u32(smem);

    const int tid  = threadIdx.x;
    const int lane = tid & 31;
    const int warp = tid >> 5;
    const int gid  = lane >> 2, tig = lane & 3;
    const int mrow = (warp >> 2) * 32;
    const int ncol = (warp & 3) * 64;

    const int which = blockIdx.y;
    const int row0  = blockIdx.x * 64;

    const float* x  = which ? xl : xg;
    const __nv_bfloat16* wT = g_wT + (size_t)which * 4 * KDIM * KDIM;
    const float* b1 = which ? lb1 : gb1;
    const float* b2 = which ? lb2 : gb2;
    const float* b3 = which ? lb3 : gb3;
    const float* bs = which ? lbs : gbs;
    __nv_bfloat16* gout = which ? g_lenc_bf : g_genc_bf;

#pragma unroll
    for (int it = 0; it < 16; it++) {
        int c   = tid + it * 256;
        int row = c >> 6;
        int kq  = (c & 63) * 4;
        float4 v = *(const float4*)(x + (size_t)(row0 + row) * KDIM + kq);
        uint2 u;
        u.x = pack_bf2(v.x, v.y);
        u.y = pack_bf2(v.z, v.w);
        *(uint2*)(smem + FF_X + (uint32_t)(row * FF_LDX + kq) * 2) = u;
    }
    __syncthreads();

    const uint32_t aL = (uint32_t)((mrow + (lane & 7) + ((lane >> 3) & 1) * 8)
                                   * FF_LDX + (lane >> 4) * 8) * 2;
    const uint32_t bL = (uint32_t)((ncol + (lane & 7) + (lane >> 4) * 8)
                                   * FF_LDW + ((lane >> 3) & 1) * 8) * 2;

    ff_gemm(smem, s_base, 0, wT + 3 * KDIM * KDIM, bs, gout, row0,
            tid, mrow, ncol, gid, tig, aL, bL);
    ff_gemm(smem, s_base, 1, wT + 0 * KDIM * KDIM, b1, gout, row0,
            tid, mrow, ncol, gid, tig, aL, bL);
    ff_gemm(smem, s_base, 1, wT + 1 * KDIM * KDIM, b2, gout, row0,
            tid, mrow, ncol, gid, tig, aL, bL);
    ff_gemm(smem, s_base, 2, wT + 2 * KDIM * KDIM, b3, gout, row0,
            tid, mrow, ncol, gid, tig, aL, bL);
}

// ============================================================================
// Per-row int8 quantization: one warp per row, absmax/127 scaling (exact RN).
// grid (1024, 2): y=0 -> g_enc (sB), y=1 -> l_enc (sA)
// ============================================================================
__global__ void __launch_bounds__(256)
quant_kernel()
{
    const int which = blockIdx.y;
    const __nv_bfloat16* src = which ? g_lenc_bf : g_genc_bf;
    char*  dst    = which ? g_lenc_i8 : g_genc_i8;
    float* scales = which ? g_sA : g_sB;

    const int lane = threadIdx.x & 31;
    const int row  = blockIdx.x * 8 + (threadIdx.x >> 5);

    uint4 v = *(const uint4*)(src + (size_t)row * KDIM + lane * 8);
    float f[8];
    {
        const uint32_t u[4] = {v.x, v.y, v.z, v.w};
#pragma unroll
        for (int i = 0; i < 4; i++) {
            float2 p = __bfloat1622float2(*(const __nv_bfloat162*)&u[i]);
            f[2 * i] = p.x; f[2 * i + 1] = p.y;
        }
    }
    float amax = 0.f;
#pragma unroll
    for (int i = 0; i < 8; i++) amax = fmaxf(amax, fabsf(f[i]));
#pragma unroll
    for (int s = 16; s > 0; s >>= 1)
        amax = fmaxf(amax, __shfl_xor_sync(0xffffffffu, amax, s));

    float scale = amax * (1.f / 127.f);
    float inv   = (amax > 0.f) ? 127.f / amax : 0.f;

    int q[8];
#pragma unroll
    for (int i = 0; i < 8; i++) {
        int t = __float2int_rn(f[i] * inv);
        q[i] = max(-127, min(127, t));
    }
    uint2 out;
    out.x = (q[0] & 255) | ((q[1] & 255) << 8) | ((q[2] & 255) << 16) | ((q[3] & 255) << 24);
    out.y = (q[4] & 255) | ((q[5] & 255) << 8) | ((q[6] & 255) << 16) | ((q[7] & 255) << 24);
    *(uint2*)(dst + (size_t)row * KDIM + lane * 8) = out;
    if (lane == 0) scales[row] = scale;
}

// ============================================================================
// Score GEMM: int8 mma.sync m16n8k32 (2x MAC rate), 128x128 CTA tile,
// 2 K-chunks of 128 int8, 2-stage cp.async, ldmatrix (b16 byte-view),
// per-row-scale dequant + fused JSD epilogue + last-block final reduce.
// SMEM: 2 stages x (A 128x144B + B 128x144B) = 73728 + scales 1024 = 74752
// ============================================================================
#define LDKB    144
#define STG_A   (128 * LDKB)
#define STG_SZ  (2 * STG_A)
#define SC_SA   (2 * STG_SZ)            // 73728: sA[128]
#define SC_SB   (SC_SA + 512)           // sB[128]
#define SM_SIZE (SC_SB + 512)           // 74752

__global__ void __launch_bounds__(256, 2)
score_kernel(const float* __restrict__ adj, float* __restrict__ out)
{
    extern __shared__ char smem[];
    const uint32_t s_base = smem_u32(smem);

    const int tid  = threadIdx.x;
    const int lane = tid & 31;
    const int warp = tid >> 5;
    const int gid  = lane >> 2;
    const int tig  = lane & 3;
    const int mrow = (warp >> 1) * 32;
    const int ncol = (warp & 1) * 64;

    const int i0 = blockIdx.y * BT;
    const int j0 = blockIdx.x * BT;

    // adj L2 prefetch (overlaps mainloop)
#pragma unroll
    for (int t = tid; t < 512; t += 256) {
        int row = t >> 2, seg = t & 3;
        prefetch_l2(adj + (size_t)(i0 + row) * NDRUGS + j0 + seg * 32);
    }

    // per-row scales into smem
    float* saF = (float*)(smem + SC_SA);
    float* sbF = (float*)(smem + SC_SB);
    if (tid < 128)       saF[tid]       = g_sA[i0 + tid];
    else                 sbF[tid - 128] = g_sB[j0 + tid - 128];

    // staging: per chunk per array 128 rows x 128 B = 1024 x 16B, 4/thread
    const int lrow = tid >> 3;          // with it*32 -> 0..127
    const int lkq  = (tid & 7) * 16;    // byte offset 0..112
    auto issue = [&](int kc, int st) {
        const uint32_t a_s = s_base + st * STG_SZ;
        const uint32_t b_s = a_s + STG_A;
#pragma unroll
        for (int it = 0; it < 4; it++) {
            int row = lrow + it * 32;
            uint32_t soff = (uint32_t)(row * LDKB + lkq);
            const size_t goff = (size_t)row * KDIM + kc * 128 + lkq;
            cp_async16(a_s + soff, g_lenc_i8 + (size_t)i0 * KDIM + goff);
            cp_async16(b_s + soff, g_genc_i8 + (size_t)j0 * KDIM + goff);
        }
        cp_async_commit();
    };

    // ldmatrix lane bases (b16 view of int8: offsets in bytes)
    const int a_row  = mrow + (lane & 7) + ((lane >> 3) & 1) * 8;
    const uint32_t a_lane = (uint32_t)(a_row * LDKB + (lane >> 4) * 16);
    const int b_row  = ncol + (lane & 7) + (lane >> 4) * 8;
    const uint32_t b_lane = (uint32_t)(b_row * LDKB + ((lane >> 3) & 1) * 16);

    int acc[2][8][4];
#pragma unroll
    for (int mt = 0; mt < 2; mt++)
#pragma unroll
        for (int nt = 0; nt < 8; nt++)
#pragma unroll
            for (int q = 0; q < 4; q++) acc[mt][nt][q] = 0;

    issue(0, 0);

#pragma unroll 1
    for (int kc = 0; kc < 2; kc++) {
        const int st = kc & 1;
        if (kc < 1) issue(kc + 1, st ^ 1);
        if (kc < 1) cp_async_wait<1>(); else cp_async_wait<0>();
        __syncthreads();

        const uint32_t a_s = s_base + st * STG_SZ + a_lane;
        const uint32_t b_s = s_base + st * STG_SZ + STG_A + b_lane;

#pragma unroll
        for (int ks = 0; ks < 4; ks++) {
            const uint32_t k0b = (uint32_t)(ks * 32);    // 32 int8 per mma
            uint32_t bfr[8][2];
#pragma unroll
            for (int ntp = 0; ntp < 4; ntp++) {
                uint32_t r0, r1, r2, r3;
                ldmatrix_x4(r0, r1, r2, r3,
                            b_s + (uint32_t)(ntp * 16 * LDKB) + k0b);
                bfr[2 * ntp][0]     = r0; bfr[2 * ntp][1]     = r1;
                bfr[2 * ntp + 1][0] = r2; bfr[2 * ntp + 1][1] = r3;
            }
#pragma unroll
            for (int mt = 0; mt < 2; mt++) {
                uint32_t a0, a1, a2, a3;
                ldmatrix_x4(a0, a1, a2, a3,
                            a_s + (uint32_t)(mt * 16 * LDKB) + k0b);
#pragma unroll
                for (int nt = 0; nt < 8; nt++)
                    mma_s8(acc[mt][nt][0], acc[mt][nt][1],
                           acc[mt][nt][2], acc[mt][nt][3],
                           a0, a1, a2, a3, bfr[nt][0], bfr[nt][1]);
            }
        }
        __syncthreads();
    }

    // ---- dequant + JSD epilogue (c = softplus(r) - LOG2) ----
    float cAcc = 0.f, pAcc = 0.f, nCorr = 0.f;
#pragma unroll
    for (int mt = 0; mt < 2; mt++) {
        const int lr = mrow + mt * 16 + gid;          // tile-local row
        const int r0 = i0 + lr;                       // global row
        const float sa0 = saF[lr], sa1 = saF[lr + 8];
#pragma unroll
        for (int nt = 0; nt < 8; nt++) {
            const int lc = ncol + nt * 8 + tig * 2;   // tile-local col
            const int c0 = j0 + lc;
            const float sb0 = sbF[lc], sb1 = sbF[lc + 1];
            float2 alo = __ldg((const float2*)(adj + (size_t)r0 * NDRUGS + c0));
            float2 ahi = __ldg((const float2*)(adj + (size_t)(r0 + 8) * NDRUGS + c0));
            float aa[4] = {alo.x, alo.y, ahi.x, ahi.y};
            float sc[4] = {sa0 * sb0, sa0 * sb1, sa1 * sb0, sa1 * sb1};
#pragma unroll
            for (int q = 0; q < 4; q++) {
                float r = (float)acc[mt][nt][q] * sc[q];
                float u = fmaxf(r, 0.f);
                float t = __logf(1.f + __expf(-fabsf(r)));
                float c = u + t - LOG2F_;   // softplus(r) - LOG2
                cAcc += c;
                if (aa[q] != 0.0f) {        // ~1% dense
                    pAcc  += r - c;         // LOG2 - softplus(-r)
                    nCorr += c;
                }
            }
        }
    }
    float pos = pAcc;
    float neg = cAcc - nCorr;

    float* red = (float*)smem;
    __syncthreads();
    red[tid] = pos; red[256 + tid] = neg;
    __syncthreads();
#pragma unroll
    for (int s = 128; s > 0; s >>= 1) {
        if (tid < s) { red[tid] += red[tid + s]; red[256 + tid] += red[256 + tid + s]; }
        __syncthreads();
    }

    // ---- publish partial, detect last block ----
    __shared__ unsigned int isLast;
    if (tid == 0) {
        int bid = blockIdx.y * gridDim.x + blockIdx.x;
        g_partials[bid]        = red[0];
        g_partials[NBLK + bid] = red[256];
        __threadfence();
        unsigned int v = atomicAdd(&g_done, 1u);
        isLast = (v == (unsigned int)(NBLK - 1)) ? 1u : 0u;
    }
    __syncthreads();

    if (isLast) {
        __threadfence();
        double* dsp = (double*)smem;
        double* dsn = dsp + 256;
        double p = 0.0, n = 0.0;
#pragma unroll 4
        for (int i = tid; i < NBLK; i += 256) {
            p += (double)g_partials[i];
            n += (double)g_partials[NBLK + i];
        }
        dsp[tid] = p; dsn[tid] = n;
        __syncthreads();
#pragma unroll
        for (int s = 128; s > 0; s >>= 1) {
            if (tid < s) { dsp[tid] += dsp[tid + s]; dsn[tid] += dsn[tid + s]; }
            __syncthreads();
        }
        if (tid == 0) {
            double E_pos = dsp[0] / (double)NDRUGS;
            double E_neg = dsn[0] / ((double)NDRUGS * (double)(NDRUGS - 1));
            out[0] = (float)(E_neg - E_pos);
            g_done = 0;   // reset for next graph replay
        }
    }
}

// ============================================================================
// launch
// ============================================================================
extern "C" void kernel_launch(void* const* d_in, const int* in_sizes, int n_in,
                              void* d_out, int out_size)
{
    const float* emb  = (const float*)d_in[0];
    const float* feat = (const float*)d_in[1];
    const float* adj  = (const float*)d_in[2];
    const float* g_w1 = (const float*)d_in[4];
    const float* g_b1 = (const float*)d_in[5];
    const float* g_w2 = (const float*)d_in[6];
    const float* g_b2 = (const float*)d_in[7];
    const float* g_w3 = (const float*)d_in[8];
    const float* g_b3 = (const float*)d_in[9];
    const float* g_ws = (const float*)d_in[10];
    const float* g_bs = (const float*)d_in[11];
    const float* l_w1 = (const float*)d_in[12];
    const float* l_b1 = (const float*)d_in[13];
    const float* l_w2 = (const float*)d_in[14];
    const float* l_b2 = (const float*)d_in[15];
    const float* l_w3 = (const float*)d_in[16];
    const float* l_b3 = (const float*)d_in[17];
    const float* l_ws = (const float*)d_in[18];
    const float* l_bs = (const float*)d_in[19];
    float* out = (float*)d_out;

    cudaFuncSetAttribute(score_kernel,
                         cudaFuncAttributeMaxDynamicSharedMemorySize, SM_SIZE);
    cudaFuncSetAttribute(ff_mma_kernel,
                         cudaFuncAttributeMaxDynamicSharedMemorySize, FF_SMEM);

    dim3 tgrid(64, 8);
    wT_kernel<<<tgrid, 256>>>(g_w1, g_w2, g_w3, g_ws, l_w1, l_w2, l_w3, l_ws);

    dim3 fgrid(NDRUGS / 64, 2);
    ff_mma_kernel<<<fgrid, 256, FF_SMEM>>>(emb, feat,
                                           g_b1, g_b2, g_b3, g_bs,
                                           l_b1, l_b2, l_b3, l_bs);

    dim3 qgrid(NDRUGS / 8, 2);
    quant_kernel<<<qgrid, 256>>>();

    dim3 grid(NDRUGS / BT, NDRUGS / BT);
    score_kernel<<<grid, 256, SM_SIZE>>>(adj, out);
}

// round 17
// speedup vs baseline: 1.5293x; 1.5293x over previous
#include <cuda_runtime.h>
#include <cuda_bf16.h>
#include <math.h>
#include <stdint.h>

// Problem constants (fixed by the dataset)
#define NDRUGS 8192
#define KDIM   256
#define LOG2F_ 0.69314718055994531f

// ============================ device scratch ================================
__device__ __align__(1024) __nv_bfloat16 g_genc_bf[NDRUGS * KDIM];
__device__ __align__(1024) __nv_bfloat16 g_lenc_bf[NDRUGS * KDIM];
__device__ __align__(1024) __nv_bfloat16 g_wT[8 * KDIM * KDIM];   // bf16 W^T

#define BT   128
#define NBLK ((NDRUGS / BT) * (NDRUGS / BT))   // 64*64 = 4096
__device__ float g_partials[2 * NBLK];
__device__ unsigned int g_done;                // zero-init; self-resetting

// =========================== small PTX helpers ==============================
__device__ __forceinline__ uint32_t smem_u32(const void* p) {
    uint32_t a;
    asm("{ .reg .u64 t; cvta.to.shared.u64 t, %1; cvt.u32.u64 %0, t; }"
        : "=r"(a) : "l"(p));
    return a;
}
__device__ __forceinline__ void cp_async16(uint32_t dst, const void* src) {
    asm volatile("cp.async.cg.shared.global [%0], [%1], 16;"
                 :: "r"(dst), "l"(src) : "memory");
}
__device__ __forceinline__ void cp_async_commit() {
    asm volatile("cp.async.commit_group;" ::: "memory");
}
template <int N>
__device__ __forceinline__ void cp_async_wait() {
    asm volatile("cp.async.wait_group %0;" :: "n"(N) : "memory");
}
__device__ __forceinline__ void prefetch_l2(const void* p) {
    asm volatile("prefetch.global.L2 [%0];" :: "l"(p));
}
__device__ __forceinline__ void ldmatrix_x4(uint32_t& r0, uint32_t& r1,
                                            uint32_t& r2, uint32_t& r3,
                                            uint32_t addr) {
    asm volatile("ldmatrix.sync.aligned.m8n8.x4.shared.b16 {%0,%1,%2,%3}, [%4];"
                 : "=r"(r0), "=r"(r1), "=r"(r2), "=r"(r3) : "r"(addr));
}
__device__ __forceinline__ void mma_bf16(float& d0, float& d1, float& d2, float& d3,
                                         uint32_t a0, uint32_t a1, uint32_t a2,
                                         uint32_t a3, uint32_t b0, uint32_t b1) {
    asm volatile(
        "mma.sync.aligned.m16n8k16.row.col.f32.bf16.bf16.f32 "
        "{%0,%1,%2,%3}, {%4,%5,%6,%7}, {%8,%9}, {%0,%1,%2,%3};"
        : "+f"(d0), "+f"(d1), "+f"(d2), "+f"(d3)
        : "r"(a0), "r"(a1), "r"(a2), "r"(a3), "r"(b0), "r"(b1));
}
__device__ __forceinline__ uint32_t pack_bf2(float a, float b) {
    __nv_bfloat162 h = __floats2bfloat162_rn(a, b);
    return *(uint32_t*)&h;
}

// ============================================================================
// Weight transpose + bf16 convert: g_wT[mat][n*256+k] = bf16(w_mat[k*256+n])
// 32x32 tiles -> grid (64, 8) = 512 blocks.
// ============================================================================
__global__ void __launch_bounds__(256)
wT_kernel(const float* __restrict__ m0, const float* __restrict__ m1,
          const float* __restrict__ m2, const float* __restrict__ m3,
          const float* __restrict__ m4, const float* __restrict__ m5,
          const float* __restrict__ m6, const float* __restrict__ m7)
{
    const float* srcs[8] = {m0, m1, m2, m3, m4, m5, m6, m7};
    const float* w = srcs[blockIdx.y];
    __nv_bfloat16* dst = g_wT + (size_t)blockIdx.y * KDIM * KDIM;

    __shared__ float t[32][33];
    const int tid = threadIdx.x;
    const int k0 = (blockIdx.x & 7) * 32;
    const int n0 = (blockIdx.x >> 3) * 32;

#pragma unroll
    for (int i = tid; i < 32 * 32; i += 256) {
        int r = i >> 5, c = i & 31;
        t[r][c] = w[(size_t)(k0 + r) * KDIM + n0 + c];
    }
    __syncthreads();
#pragma unroll
    for (int i = tid; i < 32 * 32; i += 256) {
        int r = i >> 5, c = i & 31;
        dst[(size_t)(n0 + r) * KDIM + k0 + c] = __float2bfloat16(t[c][r]);
    }
}

// ============================================================================
// Fused FF encoder via mma.sync: M=64 rows/CTA, 256 threads (8 warps 32x64),
// 2 CTAs/SM. Shortcut kept in SMEM (bf16). W single-buffered 64-col chunks.
// SMEM: X (64x264 bf16 = 33792) + TMP (same) + W (256x72 bf16 = 36864)
//     = 104448 B -> 2 CTAs/SM
// ============================================================================
#define FF_LDX  264
#define FF_LDW  72
#define FF_X    0
#define FF_TMP  33792
#define FF_W    67584
#define FF_SMEM 104448

// mode 0: out = A@W + b                       -> TMP (bf16 smem)
// mode 1: out = relu(A@W + b)                 -> X (bf16 smem, in place)
// mode 2: out = relu(A@W + b) + TMP           -> gout (bf16 global)
__device__ __forceinline__ void ff_gemm(
    char* smem, uint32_t s_base, int mode,
    const __nv_bfloat16* __restrict__ wmat, const float* __restrict__ bias,
    __nv_bfloat16* __restrict__ gout, int row0,
    int tid, int mrow, int ncol, int gid, int tig,
    uint32_t aL, uint32_t bL)
{
    float acc[2][8][4];
#pragma unroll
    for (int mt = 0; mt < 2; mt++)
#pragma unroll
        for (int nt = 0; nt < 8; nt++)
#pragma unroll
            for (int q = 0; q < 4; q++) acc[mt][nt][q] = 0.f;

    // W chunk: 256 rows x 64 bf16 = 32 KB = 2048 16B-chunks, 8 per thread
    const int wrow = tid >> 3;          // +it*32 -> 0..255
    const int wkq  = (tid & 7) * 8;     // bf16 col 0..56
    auto issueW = [&](int kc) {
        const uint32_t w_s = s_base + FF_W;
#pragma unroll
        for (int it = 0; it < 8; it++) {
            int row = wrow + it * 32;
            cp_async16(w_s + (uint32_t)(row * FF_LDW + wkq) * 2,
                       wmat + (size_t)row * KDIM + kc * 64 + wkq);
        }
        cp_async_commit();
    };

#pragma unroll 1
    for (int kc = 0; kc < 4; kc++) {
        issueW(kc);
        cp_async_wait<0>();
        __syncthreads();

        const uint32_t a_s = s_base + FF_X + aL;
        const uint32_t b_s = s_base + FF_W + bL;
#pragma unroll
        for (int ks = 0; ks < 4; ks++) {
            const uint32_t ak = (uint32_t)((kc * 64 + ks * 16) * 2);
            const uint32_t bk = (uint32_t)(ks * 16 * 2);
            uint32_t bfr[8][2];
#pragma unroll
            for (int ntp = 0; ntp < 4; ntp++) {
                uint32_t r0, r1, r2, r3;
                ldmatrix_x4(r0, r1, r2, r3,
                            b_s + (uint32_t)(ntp * 16 * FF_LDW) * 2 + bk);
                bfr[2 * ntp][0]     = r0; bfr[2 * ntp][1]     = r1;
                bfr[2 * ntp + 1][0] = r2; bfr[2 * ntp + 1][1] = r3;
            }
#pragma unroll
            for (int mt = 0; mt < 2; mt++) {
                uint32_t a0, a1, a2, a3;
                ldmatrix_x4(a0, a1, a2, a3,
                            a_s + (uint32_t)(mt * 16 * FF_LDX) * 2 + ak);
#pragma unroll
                for (int nt = 0; nt < 8; nt++)
                    mma_bf16(acc[mt][nt][0], acc[mt][nt][1],
                             acc[mt][nt][2], acc[mt][nt][3],
                             a0, a1, a2, a3, bfr[nt][0], bfr[nt][1]);
            }
        }
        __syncthreads();
    }
    // after the last barrier above, no thread reads X again -> in-place OK

    // ---- epilogue ----
#pragma unroll
    for (int mt = 0; mt < 2; mt++) {
        const int r = mrow + mt * 16 + gid;          // local row < 64
#pragma unroll
        for (int nt = 0; nt < 8; nt++) {
            const int c0 = ncol + nt * 8 + tig * 2;
            float bv0 = __ldg(bias + c0), bv1 = __ldg(bias + c0 + 1);
            float d0 = acc[mt][nt][0] + bv0, d1 = acc[mt][nt][1] + bv1;
            float d2 = acc[mt][nt][2] + bv0, d3 = acc[mt][nt][3] + bv1;
            const uint32_t off_lo = (uint32_t)(r * FF_LDX + c0) * 2;
            const uint32_t off_hi = (uint32_t)((r + 8) * FF_LDX + c0) * 2;
            if (mode == 0) {
                *(uint32_t*)(smem + FF_TMP + off_lo) = pack_bf2(d0, d1);
                *(uint32_t*)(smem + FF_TMP + off_hi) = pack_bf2(d2, d3);
            } else if (mode == 1) {
                *(uint32_t*)(smem + FF_X + off_lo) =
                    pack_bf2(fmaxf(d0, 0.f), fmaxf(d1, 0.f));
                *(uint32_t*)(smem + FF_X + off_hi) =
                    pack_bf2(fmaxf(d2, 0.f), fmaxf(d3, 0.f));
            } else {
                uint32_t ulo = *(const uint32_t*)(smem + FF_TMP + off_lo);
                uint32_t uhi = *(const uint32_t*)(smem + FF_TMP + off_hi);
                float2 t0 = __bfloat1622float2(*(__nv_bfloat162*)&ulo);
                float2 t1 = __bfloat1622float2(*(__nv_bfloat162*)&uhi);
                *(uint32_t*)(gout + (size_t)(row0 + r) * KDIM + c0) =
                    pack_bf2(fmaxf(d0, 0.f) + t0.x, fmaxf(d1, 0.f) + t0.y);
                *(uint32_t*)(gout + (size_t)(row0 + r + 8) * KDIM + c0) =
                    pack_bf2(fmaxf(d2, 0.f) + t1.x, fmaxf(d3, 0.f) + t1.y);
            }
        }
    }
    __syncthreads();   // epilogue writes visible before next GEMM reads X
}

__global__ void __launch_bounds__(256, 2)
ff_mma_kernel(const float* __restrict__ xg, const float* __restrict__ xl,
              const float* __restrict__ gb1, const float* __restrict__ gb2,
              const float* __restrict__ gb3, const float* __restrict__ gbs,
              const float* __restrict__ lb1, const float* __restrict__ lb2,
              const float* __restrict__ lb3, const float* __restrict__ lbs)
{
    extern __shared__ char smem[];
    const uint32_t s_base = smem_u32(smem);

    const int tid  = threadIdx.x;
    const int lane = tid & 31;
    const int warp = tid >> 5;
    const int gid  = lane >> 2, tig = lane & 3;
    const int mrow = (warp >> 2) * 32;   // 0..32
    const int ncol = (warp & 3) * 64;    // 0..192

    const int which = blockIdx.y;
    const int row0  = blockIdx.x * 64;

    const float* x  = which ? xl : xg;
    const __nv_bfloat16* wT = g_wT + (size_t)which * 4 * KDIM * KDIM;
    const float* b1 = which ? lb1 : gb1;
    const float* b2 = which ? lb2 : gb2;
    const float* b3 = which ? lb3 : gb3;
    const float* bs = which ? lbs : gbs;
    __nv_bfloat16* gout = which ? g_lenc_bf : g_genc_bf;

    // ---- convert input fp32 -> bf16 into X (64x256 = 4096 float4) ----
#pragma unroll
    for (int it = 0; it < 16; it++) {
        int c   = tid + it * 256;
        int row = c >> 6;
        int kq  = (c & 63) * 4;
        float4 v = *(const float4*)(x + (size_t)(row0 + row) * KDIM + kq);
        uint2 u;
        u.x = pack_bf2(v.x, v.y);
        u.y = pack_bf2(v.z, v.w);
        *(uint2*)(smem + FF_X + (uint32_t)(row * FF_LDX + kq) * 2) = u;
    }
    __syncthreads();

    const uint32_t aL = (uint32_t)((mrow + (lane & 7) + ((lane >> 3) & 1) * 8)
                                   * FF_LDX + (lane >> 4) * 8) * 2;
    const uint32_t bL = (uint32_t)((ncol + (lane & 7) + (lane >> 4) * 8)
                                   * FF_LDW + ((lane >> 3) & 1) * 8) * 2;

    // shortcut: TMP = X @ WsT + bs   (X unchanged)
    ff_gemm(smem, s_base, 0, wT + 3 * KDIM * KDIM, bs, gout, row0,
            tid, mrow, ncol, gid, tig, aL, bL);
    // h1 = relu(X @ W1T + b1) -> X
    ff_gemm(smem, s_base, 1, wT + 0 * KDIM * KDIM, b1, gout, row0,
            tid, mrow, ncol, gid, tig, aL, bL);
    // h2 = relu(X @ W2T + b2) -> X
    ff_gemm(smem, s_base, 1, wT + 1 * KDIM * KDIM, b2, gout, row0,
            tid, mrow, ncol, gid, tig, aL, bL);
    // out = relu(X @ W3T + b3) + TMP -> global bf16
    ff_gemm(smem, s_base, 2, wT + 2 * KDIM * KDIM, b3, gout, row0,
            tid, mrow, ncol, gid, tig, aL, bL);
}

// ============================================================================
// Score GEMM: mma.sync bf16, 128x128 CTA tile, 4 K-chunks of 64, 2-stage
// cp.async pipeline, ldmatrix, fused JSD epilogue + last-block final reduce.
// Epilogue algebra: c = softplus(r) - LOG2;  neg-term = c;  pos-term = r - c.
// ============================================================================
#define LDK     72
#define STG_A   (128 * LDK * 2)
#define STG_SZ  (2 * STG_A)
#define SM_SIZE (2 * STG_SZ)

__global__ void __launch_bounds__(256, 2)
score_kernel(const float* __restrict__ adj, float* __restrict__ out)
{
    extern __shared__ char smem[];
    const uint32_t s_base = smem_u32(smem);

    const int tid  = threadIdx.x;
    const int lane = tid & 31;
    const int warp = tid >> 5;
    const int gid  = lane >> 2;
    const int tig  = lane & 3;
    const int mrow = (warp >> 1) * 32;
    const int ncol = (warp & 1) * 64;

    const int i0 = blockIdx.y * BT;
    const int j0 = blockIdx.x * BT;

#pragma unroll
    for (int t = tid; t < 512; t += 256) {
        int row = t >> 2, seg = t & 3;
        prefetch_l2(adj + (size_t)(i0 + row) * NDRUGS + j0 + seg * 32);
    }

    const int lrow = tid >> 3;
    const int lkq  = (tid & 7) * 8;
    auto issue = [&](int kc, int st) {
        const uint32_t a_s = s_base + st * STG_SZ;
        const uint32_t b_s = a_s + STG_A;
#pragma unroll
        for (int it = 0; it < 4; it++) {
            int row = lrow + it * 32;
            uint32_t soff = (uint32_t)(row * LDK + lkq) * 2;
            const size_t goff = (size_t)row * KDIM + kc * 64 + lkq;
            cp_async16(a_s + soff, g_lenc_bf + (size_t)i0 * KDIM + goff);
            cp_async16(b_s + soff, g_genc_bf + (size_t)j0 * KDIM + goff);
        }
        cp_async_commit();
    };

    const int a_row  = mrow + (lane & 7) + ((lane >> 3) & 1) * 8;
    const int a_koff = (lane >> 4) * 8;
    const uint32_t a_lane = (uint32_t)(a_row * LDK + a_koff) * 2;
    const int b_row  = ncol + (lane & 7) + (lane >> 4) * 8;
    const int b_koff = ((lane >> 3) & 1) * 8;
    const uint32_t b_lane = (uint32_t)(b_row * LDK + b_koff) * 2;

    float acc[2][8][4];
#pragma unroll
    for (int mt = 0; mt < 2; mt++)
#pragma unroll
        for (int nt = 0; nt < 8; nt++)
#pragma unroll
            for (int q = 0; q < 4; q++) acc[mt][nt][q] = 0.f;

    issue(0, 0);

#pragma unroll 1
    for (int kc = 0; kc < 4; kc++) {
        const int st = kc & 1;
        if (kc < 3) issue(kc + 1, st ^ 1);
        if (kc < 3) cp_async_wait<1>(); else cp_async_wait<0>();
        __syncthreads();

        const uint32_t a_s = s_base + st * STG_SZ + a_lane;
        const uint32_t b_s = s_base + st * STG_SZ + STG_A + b_lane;

#pragma unroll
        for (int ks = 0; ks < 4; ks++) {
            const uint32_t k0b = (uint32_t)(ks * 16) * 2;
            uint32_t bfr[8][2];
#pragma unroll
            for (int ntp = 0; ntp < 4; ntp++) {
                uint32_t r0, r1, r2, r3;
                ldmatrix_x4(r0, r1, r2, r3,
                            b_s + (uint32_t)(ntp * 16 * LDK) * 2 + k0b);
                bfr[2 * ntp][0]     = r0; bfr[2 * ntp][1]     = r1;
                bfr[2 * ntp + 1][0] = r2; bfr[2 * ntp + 1][1] = r3;
            }
#pragma unroll
            for (int mt = 0; mt < 2; mt++) {
                uint32_t a0, a1, a2, a3;
                ldmatrix_x4(a0, a1, a2, a3,
                            a_s + (uint32_t)(mt * 16 * LDK) * 2 + k0b);
#pragma unroll
                for (int nt = 0; nt < 8; nt++)
                    mma_bf16(acc[mt][nt][0], acc[mt][nt][1],
                             acc[mt][nt][2], acc[mt][nt][3],
                             a0, a1, a2, a3, bfr[nt][0], bfr[nt][1]);
            }
        }
        __syncthreads();
    }

    // ---- epilogue: cAcc over all, rare pos-branch corrections ----
    float cAcc = 0.f, pAcc = 0.f, nCorr = 0.f;
#pragma unroll
    for (int mt = 0; mt < 2; mt++) {
        const int r0 = i0 + mrow + mt * 16 + gid;
#pragma unroll
        for (int nt = 0; nt < 8; nt++) {
            const int c0 = j0 + ncol + nt * 8 + tig * 2;
            float2 alo = __ldg((const float2*)(adj + (size_t)r0 * NDRUGS + c0));
            float2 ahi = __ldg((const float2*)(adj + (size_t)(r0 + 8) * NDRUGS + c0));
            float aa[4] = {alo.x, alo.y, ahi.x, ahi.y};
#pragma unroll
            for (int q = 0; q < 4; q++) {
                float r = acc[mt][nt][q];
                float u = fmaxf(r, 0.f);
                float t = __logf(1.f + __expf(-fabsf(r)));
                float c = u + t - LOG2F_;   // softplus(r) - LOG2
                cAcc += c;
                if (aa[q] != 0.0f) {        // ~1% dense
                    pAcc  += r - c;         // LOG2 - softplus(-r)
                    nCorr += c;
                }
            }
        }
    }
    float pos = pAcc;
    float neg = cAcc - nCorr;

    float* red = (float*)smem;
    __syncthreads();
    red[tid] = pos; red[256 + tid] = neg;
    __syncthreads();
#pragma unroll
    for (int s = 128; s > 0; s >>= 1) {
        if (tid < s) { red[tid] += red[tid + s]; red[256 + tid] += red[256 + tid + s]; }
        __syncthreads();
    }

    // ---- publish partial, detect last block ----
    __shared__ unsigned int isLast;
    if (tid == 0) {
        int bid = blockIdx.y * gridDim.x + blockIdx.x;
        g_partials[bid]        = red[0];
        g_partials[NBLK + bid] = red[256];
        __threadfence();
        unsigned int v = atomicAdd(&g_done, 1u);
        isLast = (v == (unsigned int)(NBLK - 1)) ? 1u : 0u;
    }
    __syncthreads();

    // ---- last block performs the deterministic final reduction ----
    if (isLast) {
        __threadfence();
        double* dsp = (double*)smem;
        double* dsn = dsp + 256;
        double p = 0.0, n = 0.0;
#pragma unroll 4
        for (int i = tid; i < NBLK; i += 256) {
            p += (double)g_partials[i];
            n += (double)g_partials[NBLK + i];
        }
        dsp[tid] = p; dsn[tid] = n;
        __syncthreads();
#pragma unroll
        for (int s = 128; s > 0; s >>= 1) {
            if (tid < s) { dsp[tid] += dsp[tid + s]; dsn[tid] += dsn[tid + s]; }
            __syncthreads();
        }
        if (tid == 0) {
            double E_pos = dsp[0] / (double)NDRUGS;
            double E_neg = dsn[0] / ((double)NDRUGS * (double)(NDRUGS - 1));
            out[0] = (float)(E_neg - E_pos);
            g_done = 0;   // reset for next graph replay
        }
    }
}

// ============================================================================
// launch
// ============================================================================
extern "C" void kernel_launch(void* const* d_in, const int* in_sizes, int n_in,
                              void* d_out, int out_size)
{
    const float* emb  = (const float*)d_in[0];
    const float* feat = (const float*)d_in[1];
    const float* adj  = (const float*)d_in[2];
    const float* g_w1 = (const float*)d_in[4];
    const float* g_b1 = (const float*)d_in[5];
    const float* g_w2 = (const float*)d_in[6];
    const float* g_b2 = (const float*)d_in[7];
    const float* g_w3 = (const float*)d_in[8];
    const float* g_b3 = (const float*)d_in[9];
    const float* g_ws = (const float*)d_in[10];
    const float* g_bs = (const float*)d_in[11];
    const float* l_w1 = (const float*)d_in[12];
    const float* l_b1 = (const float*)d_in[13];
    const float* l_w2 = (const float*)d_in[14];
    const float* l_b2 = (const float*)d_in[15];
    const float* l_w3 = (const float*)d_in[16];
    const float* l_b3 = (const float*)d_in[17];
    const float* l_ws = (const float*)d_in[18];
    const float* l_bs = (const float*)d_in[19];
    float* out = (float*)d_out;

    cudaFuncSetAttribute(score_kernel,
                         cudaFuncAttributeMaxDynamicSharedMemorySize, SM_SIZE);
    cudaFuncSetAttribute(ff_mma_kernel,
                         cudaFuncAttributeMaxDynamicSharedMemorySize, FF_SMEM);

    dim3 tgrid(64, 8);
    wT_kernel<<<tgrid, 256>>>(g_w1, g_w2, g_w3, g_ws, l_w1, l_w2, l_w3, l_ws);

    dim3 fgrid(NDRUGS / 64, 2);
    ff_mma_kernel<<<fgrid, 256, FF_SMEM>>>(emb, feat,
                                           g_b1, g_b2, g_b3, g_bs,
                                           l_b1, l_b2, l_b3, l_bs);

    dim3 grid(NDRUGS / BT, NDRUGS / BT);
    score_kernel<<<grid, 256, SM_SIZE>>>(adj, out);
}